// round 6
// baseline (speedup 1.0000x reference)
#include <cuda_runtime.h>

// DigitCaps broadcasted batched matvec:
//   u_hat[b,r,c,o] = sum_i W[r,c,o,i] * x[b,r,i] + bias[o]
// B=512, R=1152, C=10, O=16, I=8, fp32.
//
// R4: W-stationary register dataflow. Previous smem-staged versions were
// L1-bound on W LDS.128 traffic (128B of W through the crossbar per 16B of
// output). Now each thread owns one (c,o) pair's 8 W floats in registers for
// the whole kernel and loops over all 512 batch elements:
//   - W smem traffic: zero; W read once from DRAM (5.9 MB).
//   - x: 2 uniform-address LDG.128 per warp per b (broadcast, L1-resident).
//   - stores: warp = 32 consecutive floats = one 128B line per STG instr
//     (the coalescing floor, 2.95M wavefronts total).
// Leaves DRAM (~400 MB compulsory) as the binding resource.

#define DC_B 512
#define DC_R 1152
#define DC_C 10
#define DC_O 16
#define DC_I 8

#define CO (DC_C * DC_O)          // 160 threads per block = one r
#define BU 4                      // batch unroll

__global__ __launch_bounds__(CO)
void digitcaps_kernel(const float* __restrict__ x,
                      const float* __restrict__ W,
                      const float* __restrict__ bias,
                      float* __restrict__ out)
{
    const int tid = threadIdx.x;          // tid = c*16 + o
    const int r   = blockIdx.x;
    const int o   = tid & 15;

    // ---- W for this thread's (r, c, o): 8 consecutive floats, coalesced ----
    const float4* wp = reinterpret_cast<const float4*>(
        W + (size_t)r * (DC_C * DC_O * DC_I) + (size_t)tid * DC_I);
    const float4 wa = wp[0];
    const float4 wb = wp[1];

    const float bo = __ldg(bias + o);

    // x[b, r, 0:8]: base for b=0, stride R*I floats per b
    const float4* xp = reinterpret_cast<const float4*>(x + (size_t)r * DC_I);
    const size_t xstride4 = (size_t)DC_R * DC_I / 4;      // float4 stride per b

    // out[((b*R + r)*C + c)*O + o]: base for b=0, stride R*C*O floats per b
    float* op = out + (size_t)r * CO + tid;
    const size_t ostride = (size_t)DC_R * CO;

#pragma unroll 1
    for (int b = 0; b < DC_B; b += BU) {
        float4 xa[BU], xb[BU];
#pragma unroll
        for (int u = 0; u < BU; ++u) {
            xa[u] = xp[(size_t)u * xstride4];
            xb[u] = xp[(size_t)u * xstride4 + 1];
        }
#pragma unroll
        for (int u = 0; u < BU; ++u) {
            float acc;
            acc = fmaf(wa.x, xa[u].x, fmaf(wa.y, xa[u].y,
                  fmaf(wa.z, xa[u].z, fmaf(wa.w, xa[u].w,
                  fmaf(wb.x, xb[u].x, fmaf(wb.y, xb[u].y,
                  fmaf(wb.z, xb[u].z, fmaf(wb.w, xb[u].w, bo))))))));
            op[(size_t)u * ostride] = acc;
        }
        xp += (size_t)BU * xstride4;
        op += (size_t)BU * ostride;
    }
}

extern "C" void kernel_launch(void* const* d_in, const int* in_sizes, int n_in,
                              void* d_out, int out_size)
{
    const float* x    = (const float*)d_in[0];  // [B, R, I]
    const float* W    = (const float*)d_in[1];  // [1, R, C, O, I]
    const float* bias = (const float*)d_in[2];  // [O, 1]
    float* out = (float*)d_out;                 // [B, R, C, O, 1]

    dim3 block(CO, 1, 1);        // 160
    dim3 grid(DC_R, 1, 1);       // 1152
    digitcaps_kernel<<<grid, block>>>(x, W, bias, out);
}

// round 7
// speedup vs baseline: 2.1548x; 2.1548x over previous
#include <cuda_runtime.h>

// DigitCaps broadcasted batched matvec:
//   u_hat[b,r,c,o] = sum_i W[r,c,o,i] * x[b,r,i] + bias[o]
// B=512, R=1152, C=10, O=16, I=8, fp32.
//
// R5: R2 dataflow (BT=16 W-amortization, padded smem, 4-wavefront stores)
// with a smaller CTA to raise occupancy without changing per-output traffic:
//   - RB 8 -> 4, block 128 (warp w = r_local), smem 47KB -> 25KB
//   - x read per-k from smem (broadcast LDS, 1 wf/instr) instead of held in
//     regs: regs ~89 -> ~70 -> up to 7 CTAs/SM = 28 warps (vs 16 in R2)
//   - x tile per block = 16 x one whole 128B line (perfect coalescing,
//     each x line read exactly once chip-wide)
//   - __stcs stores keep the 377MB output stream from evicting L2-resident W
// Lane = bg(4) x c2(2) x o4(4). Each thread: 4 b's (k) x 2 c's x 4 o's.

#define DC_B 512
#define DC_R 1152
#define DC_C 10
#define DC_O 16
#define DC_I 8

#define RB 4     // r rows per block (one per warp)
#define BT 16    // batch elems per block
// smem W: 4r * 10c * 4(o4) rows of 36 floats = 5760 floats (23KB)
// smem x: 16 b * 36 floats (32 data + 4 pad)  =  576 floats
#define SW_FLOATS 5760
#define SX_FLOATS 576
#define SMEM_BYTES ((SW_FLOATS + SX_FLOATS) * 4)

__global__ __launch_bounds__(128, 7)
void digitcaps_kernel(const float* __restrict__ x,
                      const float* __restrict__ W,
                      const float* __restrict__ bias,
                      float* __restrict__ out)
{
    extern __shared__ float smem[];
    float* sW = smem;                 // [g][36], g = (r_local*10 + c)*4 + o4
    float* sx = smem + SW_FLOATS;     // [b_local][36]: 4 r * 8 i + pad

    const int tid = threadIdx.x;
    const int r0  = blockIdx.x * RB;
    const int b0  = blockIdx.y * BT;

    // ---- cooperative W load: 4 r rows * 1280 floats = 1280 float4, coalesced ----
    {
        const float4* Wg = reinterpret_cast<const float4*>(W + (size_t)r0 * (DC_C * DC_O * DC_I));
#pragma unroll
        for (int q4 = 0; q4 < 10; ++q4) {
            const int q = q4 * 128 + tid;           // float4 index in W tile
            const float4 v = Wg[q];
            // q -> (rc, o, ih): flat = ((rc)*16 + o)*2 + ih
            const int ih = q & 1;
            const int o  = (q >> 1) & 15;
            const int rc = q >> 5;                   // r_local*10 + c
            const int g  = rc * 4 + (o >> 2);
            *reinterpret_cast<float4*>(sW + g * 36 + (o & 3) * 8 + ih * 4) = v;
        }
    }
    // ---- cooperative x load: 16 b * 32 floats = 128 float4 (one per thread),
    //      each b = exactly one 128B line of x ----
    {
        const int b_i = tid >> 3;                    // 0..15
        const int m   = tid & 7;                     // float4 index within line
        const float4 v = *reinterpret_cast<const float4*>(
            x + ((size_t)(b0 + b_i) * DC_R + r0) * DC_I + m * 4);
        *reinterpret_cast<float4*>(sx + b_i * 36 + m * 4) = v;
    }
    __syncthreads();

    const int lane = tid & 31;
    const int w    = tid >> 5;       // warp id == r_local (0..3)
    const int bg   = lane >> 3;      // 0..3 batch group
    const int c2   = (lane >> 2) & 1;
    const int o4   = lane & 3;

    const int r = r0 + w;

    const float4 bb = *reinterpret_cast<const float4*>(bias + o4 * 4);

    // out element offset: ((b*R + r)*C + c)*O + o
    const size_t out_r = (size_t)r * (DC_C * DC_O);

#pragma unroll
    for (int cp = 0; cp < 5; ++cp) {
        const int c = cp * 2 + c2;
        // W row for (r, c, o4): 32 floats = 4 o * 8 i. 8 consecutive g-rows per
        // warp, row stride 36 floats -> 8 distinct 16B banks, conflict-free.
        const float* wr = sW + ((w * DC_C + c) * 4 + o4) * 36;
        const float4 w0a = *reinterpret_cast<const float4*>(wr + 0);
        const float4 w0b = *reinterpret_cast<const float4*>(wr + 4);
        const float4 w1a = *reinterpret_cast<const float4*>(wr + 8);
        const float4 w1b = *reinterpret_cast<const float4*>(wr + 12);
        const float4 w2a = *reinterpret_cast<const float4*>(wr + 16);
        const float4 w2b = *reinterpret_cast<const float4*>(wr + 20);
        const float4 w3a = *reinterpret_cast<const float4*>(wr + 24);
        const float4 w3b = *reinterpret_cast<const float4*>(wr + 28);

#pragma unroll
        for (int k = 0; k < 4; ++k) {
            const int bl = k * 4 + bg;
            // broadcast LDS: one address per 8-lane phase -> 1 wavefront
            const float4 va = *reinterpret_cast<const float4*>(sx + bl * 36 + w * 8);
            const float4 vb = *reinterpret_cast<const float4*>(sx + bl * 36 + w * 8 + 4);

            float4 acc;
            acc.x = fmaf(w0a.x, va.x, fmaf(w0a.y, va.y,
                    fmaf(w0a.z, va.z, fmaf(w0a.w, va.w,
                    fmaf(w0b.x, vb.x, fmaf(w0b.y, vb.y,
                    fmaf(w0b.z, vb.z, fmaf(w0b.w, vb.w, bb.x))))))));
            acc.y = fmaf(w1a.x, va.x, fmaf(w1a.y, va.y,
                    fmaf(w1a.z, va.z, fmaf(w1a.w, va.w,
                    fmaf(w1b.x, vb.x, fmaf(w1b.y, vb.y,
                    fmaf(w1b.z, vb.z, fmaf(w1b.w, vb.w, bb.y))))))));
            acc.z = fmaf(w2a.x, va.x, fmaf(w2a.y, va.y,
                    fmaf(w2a.z, va.z, fmaf(w2a.w, va.w,
                    fmaf(w2b.x, vb.x, fmaf(w2b.y, vb.y,
                    fmaf(w2b.z, vb.z, fmaf(w2b.w, vb.w, bb.z))))))));
            acc.w = fmaf(w3a.x, va.x, fmaf(w3a.y, va.y,
                    fmaf(w3a.z, va.z, fmaf(w3a.w, va.w,
                    fmaf(w3b.x, vb.x, fmaf(w3b.y, vb.y,
                    fmaf(w3b.z, vb.z, fmaf(w3b.w, vb.w, bb.w))))))));

            const int b = b0 + bl;
            // Per STG warp instr: 4 x 128B contiguous segments -> 4 wavefronts.
            float4* op = reinterpret_cast<float4*>(
                out + (size_t)b * (DC_R * DC_C * DC_O) + out_r
                    + (size_t)c * DC_O + o4 * 4);
            __stcs(op, acc);
        }
    }
}

extern "C" void kernel_launch(void* const* d_in, const int* in_sizes, int n_in,
                              void* d_out, int out_size)
{
    const float* x    = (const float*)d_in[0];  // [B, R, I]
    const float* W    = (const float*)d_in[1];  // [1, R, C, O, I]
    const float* bias = (const float*)d_in[2];  // [O, 1]
    float* out = (float*)d_out;                 // [B, R, C, O, 1]

    cudaFuncSetAttribute(digitcaps_kernel,
                         cudaFuncAttributeMaxDynamicSharedMemorySize, SMEM_BYTES);

    dim3 block(128, 1, 1);
    dim3 grid(DC_R / RB, DC_B / BT, 1);   // (288, 32)
    digitcaps_kernel<<<grid, block, SMEM_BYTES>>>(x, W, bias, out);
}